// round 12
// baseline (speedup 1.0000x reference)
#include <cuda_runtime.h>
#include <cuda_bf16.h>
#include <cstdint>

#define NA     8192
#define NBND   32768
#define NG     256
#define EMB    32
#define DEPTH  10
#define WPR    256            // 8192 bits / 32 = mask words per row
#define SPLITK 4
#define KSPLIT (NA / SPLITK)  // 2048 k per split
#define NCHUNK (KSPLIT / 128) // 16 chunks of 128 k
#define SCALE_F 16384.0f

#define OUT_H_OFF     0
#define OUT_BOND_OFF  (NA * EMB)                 // 262144
#define OUT_GRAPH_OFF (NA * EMB + NBND * EMB)    // 1310720

// ---------------- static device scratch (no allocation) ----------------
__device__ __align__(16) unsigned int  g_mask[NA * WPR];       // 8 MB bitmask (natural bit order)
__device__ float                       g_invdeg[NA];            // 1/(S*deg), 0 if deg==0
__device__ __align__(16) float         g_h[NA * EMB];           // current h (fp32)
__device__ __align__(16) unsigned char g_Bq[NA * EMB * 2];      // int8 hi/lo planes, b-frag layout (512 KB)
__device__ __align__(16) int           g_nm[SPLITK * NA * EMB]; // split-K int32 partials of A@hq (4 MB)
__device__ float                       g_Wf[DEPTH * 96 * 64];   // wih @ msg_W (folded)
__device__ float                       g_bf[DEPTH * 96];        // wih @ msg_b + b_ih
__device__ float                       g_gm[NG * EMB];          // graph means

// ---------------- helpers ----------------
__device__ __forceinline__ uint32_t smem_u32(const void* p) {
    return (uint32_t)__cvta_generic_to_shared(p);
}
__device__ __forceinline__ void cp_async16(uint32_t dst, const void* src) {
    asm volatile("cp.async.ca.shared.global [%0], [%1], 16;" :: "r"(dst), "l"(src) : "memory");
}
// expand 4 mask bits -> 4 bytes of 0/1 packed in a u32 (no carries: bit j lands at 8j)
__device__ __forceinline__ unsigned expand4(unsigned nib) {
    return (nib * 0x00204081u) & 0x01010101u;
}

// ---------------- one-time: adjacency -> bitmask + 1/(S*deg) ----------------
__global__ void k_mask(const int* __restrict__ adj) {
    int row = blockIdx.x;
    int warp = threadIdx.x >> 5, lane = threadIdx.x & 31;
    const int* arow = adj + (long long)row * NA;
    int cnt = 0;
    for (int wb = 0; wb < 32; wb++) {
        int col = wb * 256 + warp * 32 + lane;
        int v = arow[col] > 0;
        cnt += v;
        unsigned bits = __ballot_sync(0xFFFFFFFFu, v);
        if (lane == 0) g_mask[row * WPR + wb * 8 + warp] = bits;
    }
    __shared__ int s[256];
    s[threadIdx.x] = cnt;
    __syncthreads();
    for (int st = 128; st > 0; st >>= 1) {
        if (threadIdx.x < st) s[threadIdx.x] += s[threadIdx.x + st];
        __syncthreads();
    }
    if (threadIdx.x == 0) {
        int deg = s[0];
        g_invdeg[row] = deg > 0 ? 1.0f / (SCALE_F * (float)deg) : 0.0f;
    }
}

// ---------------- one-time: fold wih@W and wih@b + b_ih ----------------
__global__ void k_fold(const float* __restrict__ msg_W, const float* __restrict__ msg_b,
                       const float* __restrict__ wih, const float* __restrict__ bih) {
    int d = blockIdx.y;
    int idx = blockIdx.x * 256 + threadIdx.x;
    if (idx >= 96 * 64) return;
    int q = idx >> 6, kk = idx & 63;
    const float* wr = wih + (d * 96 + q) * 256;
    const float* Wc = msg_W + d * 256 * 64 + kk;
    float acc = 0.f;
#pragma unroll 8
    for (int m = 0; m < 256; m++) acc += wr[m] * Wc[m * 64];
    g_Wf[(d * 96 + q) * 64 + kk] = acc;
    if (kk == 0) {
        const float* bm = msg_b + d * 256;
        float a = 0.f;
        for (int m = 0; m < 256; m++) a += wr[m] * bm[m];
        g_bf[d * 96 + q] = a + bih[d * 96 + q];
    }
}

// ---------------- int16 fixed-point split of h into b-fragment byte layout ----------------
// g_Bq uint2-unit index: ((c32*2 + plane)*4 + nt)*32 + t*8 + g
//   c32 = i>>5 (k32 chunk), t = (i>>2)&3, half = (i>>4)&1 (selects .x/.y), bp = i&3
//   nt = c>>3, g = c&7
__device__ __forceinline__ void store_Bq(int i, int c, float h) {
    int hq = __float2int_rn(h * SCALE_F);
    hq = max(-32768, min(32767, hq));
    int hi = hq >> 8;          // arithmetic: hq = 256*hi + lo, lo in [0,255]
    int lo = hq & 255;
    int c32 = i >> 5;
    int t = (i >> 2) & 3, half = (i >> 4) & 1, bp = i & 3;
    int nt = c >> 3, gg = c & 7;
    size_t u2 = ((size_t)(c32 * 8) + nt) * 32 + t * 8 + gg;     // plane 0
    size_t b0 = u2 * 8 + half * 4 + bp;
    g_Bq[b0]        = (unsigned char)(hi & 0xFF);               // s8 plane
    g_Bq[b0 + 1024] = (unsigned char)lo;                        // u8 plane (+4*32*8 bytes)
}

// ---------------- one-time: atom embedding gather ----------------
__global__ void k_embed(const int* __restrict__ af, const float* __restrict__ emb) {
    int idx = blockIdx.x * 256 + threadIdx.x;   // 8192*32
    int i = idx >> 5, c = idx & 31;
    float h = emb[af[i] * EMB + c];
    g_h[idx] = h;
    store_Bq(i, c, h);
}

// ---------------- per-layer: A@hq via int8 mma.sync (exact) ----------------
__device__ __forceinline__ void mma_u8s8(int* c, const unsigned* a, unsigned b0, unsigned b1) {
    asm volatile(
        "mma.sync.aligned.m16n8k32.row.col.s32.u8.s8.s32 "
        "{%0,%1,%2,%3}, {%4,%5,%6,%7}, {%8,%9}, {%0,%1,%2,%3};"
        : "+r"(c[0]), "+r"(c[1]), "+r"(c[2]), "+r"(c[3])
        : "r"(a[0]), "r"(a[1]), "r"(a[2]), "r"(a[3]), "r"(b0), "r"(b1));
}
__device__ __forceinline__ void mma_u8u8(int* c, const unsigned* a, unsigned b0, unsigned b1) {
    asm volatile(
        "mma.sync.aligned.m16n8k32.row.col.s32.u8.u8.s32 "
        "{%0,%1,%2,%3}, {%4,%5,%6,%7}, {%8,%9}, {%0,%1,%2,%3};"
        : "+r"(c[0]), "+r"(c[1]), "+r"(c[2]), "+r"(c[3])
        : "r"(a[0]), "r"(a[1]), "r"(a[2]), "r"(a[3]), "r"(b0), "r"(b1));
}

// CTA: 128 threads = 4 warps, CTA tile M=64, warp tile m16 x N=32 (both planes).
// Chunk = 128 k (4 x k32). B chunk = 8 KB contiguous in g_Bq, double-buffered SMEM.
__global__ void __launch_bounds__(128, 4) k_adj() {
    __shared__ __align__(16) unsigned char sB[2][8192];
    int tid = threadIdx.x;
    int warp = tid >> 5, lane = tid & 31;
    int g = lane >> 2, t = lane & 3;
    int t8g = t * 8 + g;
    int sh0 = 4 * t, sh1 = 16 + 4 * t;
    int bm = blockIdx.x, sk = blockIdx.y;
    int rw = bm * 64 + warp * 16;
    int r0 = rw + g, r1 = rw + 8 + g;

    int acch[4][4], accl[4][4];
#pragma unroll
    for (int nt = 0; nt < 4; nt++)
#pragma unroll
        for (int q = 0; q < 4; q++) { acch[nt][q] = 0; accl[nt][q] = 0; }

    int kw0 = sk * (KSPLIT / 32);   // first mask word of this split

    auto issue = [&](int ch) {
        unsigned char* dst = sB[ch & 1];
        const unsigned char* src = g_Bq + (size_t)(kw0 + ch * 4) * 2048;
#pragma unroll
        for (int j = 0; j < 4; j++) {
            int off = (tid + j * 128) * 16;
            cp_async16(smem_u32(dst + off), src + off);
        }
        asm volatile("cp.async.commit_group;" ::: "memory");
    };

    issue(0);
    uint4 p0 = *reinterpret_cast<const uint4*>(&g_mask[r0 * WPR + kw0]);
    uint4 p1 = *reinterpret_cast<const uint4*>(&g_mask[r1 * WPR + kw0]);

    for (int ch = 0; ch < NCHUNK; ch++) {
        unsigned mw0[4] = { p0.x, p0.y, p0.z, p0.w };
        unsigned mw1[4] = { p1.x, p1.y, p1.z, p1.w };
        if (ch + 1 < NCHUNK) {
            issue(ch + 1);
            p0 = *reinterpret_cast<const uint4*>(&g_mask[r0 * WPR + kw0 + (ch + 1) * 4]);
            p1 = *reinterpret_cast<const uint4*>(&g_mask[r1 * WPR + kw0 + (ch + 1) * 4]);
            asm volatile("cp.async.wait_group 1;" ::: "memory");
        } else {
            asm volatile("cp.async.wait_group 0;" ::: "memory");
        }
        __syncthreads();

        const uint2* sb2 = reinterpret_cast<const uint2*>(sB[ch & 1]);
#pragma unroll
        for (int w = 0; w < 4; w++) {
            unsigned m0 = mw0[w], m1 = mw1[w];
            unsigned a[4];
            a[0] = expand4((m0 >> sh0) & 15);
            a[1] = expand4((m1 >> sh0) & 15);
            a[2] = expand4((m0 >> sh1) & 15);
            a[3] = expand4((m1 >> sh1) & 15);
            const uint2* base = sb2 + w * 256;   // ((w*2+p)*4+nt)*32 : p adds 128, nt adds 32
#pragma unroll
            for (int nt = 0; nt < 4; nt++) {
                uint2 bh = base[nt * 32 + t8g];
                uint2 bl = base[128 + nt * 32 + t8g];
                mma_u8s8(acch[nt], a, bh.x, bh.y);
                mma_u8u8(accl[nt], a, bl.x, bl.y);
            }
        }
        __syncthreads();
    }

    // epilogue: combine 256*hi + lo (exact int32), write int partials
    int* out = g_nm + (size_t)sk * NA * EMB;
#pragma unroll
    for (int nt = 0; nt < 4; nt++) {
        int col = nt * 8 + 2 * t;
        int2 v0, v1;
        v0.x = acch[nt][0] * 256 + accl[nt][0];
        v0.y = acch[nt][1] * 256 + accl[nt][1];
        v1.x = acch[nt][2] * 256 + accl[nt][2];
        v1.y = acch[nt][3] * 256 + accl[nt][3];
        *reinterpret_cast<int2*>(&out[r0 * EMB + col]) = v0;
        *reinterpret_cast<int2*>(&out[r1 * EMB + col]) = v1;
    }
}

// ---------------- per-layer: fused msg-fold + GRU update (4 atoms per warp) ----------------
__global__ void __launch_bounds__(256) k_gru(int d,
        const float* __restrict__ whh, const float* __restrict__ bih,
        const float* __restrict__ bhh, float* __restrict__ outH) {
    __shared__ float sWf[64 * 97];   // transposed, pad 97 -> conflict-free
    __shared__ float sWh[32 * 97];
    __shared__ float sbf[96], sbi[96], sbh[96];
    __shared__ float sx[32][64];
    int tid = threadIdx.x;

    const float* Wf = g_Wf + d * 96 * 64;
    for (int idx = tid; idx < 96 * 64; idx += 256) {
        int q = idx >> 6, k = idx & 63;
        sWf[k * 97 + q] = Wf[idx];
    }
    const float* Wh = whh + d * 96 * 32;
    for (int idx = tid; idx < 96 * 32; idx += 256) {
        int q = idx >> 5, k = idx & 31;
        sWh[k * 97 + q] = Wh[idx];
    }
    if (tid < 96) {
        sbf[tid] = g_bf[d * 96 + tid];
        sbi[tid] = bih[d * 96 + tid];
        sbh[tid] = bhh[d * 96 + tid];
    }

    int w = tid >> 5, c = tid & 31;
    int abase = blockIdx.x * 32 + w * 4;
    float hc[4], inv[4];
#pragma unroll
    for (int a = 0; a < 4; a++) {
        int atom = abase + a;
        hc[a]  = g_h[atom * EMB + c];
        inv[a] = g_invdeg[atom];
        int nmi = 0;
#pragma unroll
        for (int s = 0; s < SPLITK; s++)
            nmi += g_nm[(size_t)s * NA * EMB + atom * EMB + c];
        sx[w * 4 + a][c]      = hc[a];
        sx[w * 4 + a][32 + c] = (float)nmi * inv[a];
    }
    __syncthreads();

    float ir[4]  = {0, 0, 0, 0}, iz[4] = {0, 0, 0, 0}, inn[4] = {0, 0, 0, 0};
    float hr[4]  = {0, 0, 0, 0}, hz[4] = {0, 0, 0, 0}, hn[4]  = {0, 0, 0, 0};
#pragma unroll 8
    for (int k = 0; k < 32; k++) {
        float wf0 = sWf[k * 97 + c], wf1 = sWf[k * 97 + 32 + c], wf2 = sWf[k * 97 + 64 + c];
        float wh0 = sWh[k * 97 + c], wh1 = sWh[k * 97 + 32 + c], wh2 = sWh[k * 97 + 64 + c];
#pragma unroll
        for (int a = 0; a < 4; a++) {
            float xk = sx[w * 4 + a][k];
            ir[a]  += xk * wf0; iz[a] += xk * wf1; inn[a] += xk * wf2;
            hr[a]  += xk * wh0; hz[a] += xk * wh1; hn[a]  += xk * wh2;
        }
    }
#pragma unroll 8
    for (int k = 32; k < 64; k++) {
        float wf0 = sWf[k * 97 + c], wf1 = sWf[k * 97 + 32 + c], wf2 = sWf[k * 97 + 64 + c];
#pragma unroll
        for (int a = 0; a < 4; a++) {
            float xk = sx[w * 4 + a][k];
            ir[a] += xk * wf0; iz[a] += xk * wf1; inn[a] += xk * wf2;
        }
    }

#pragma unroll
    for (int a = 0; a < 4; a++) {
        int atom = abase + a;
        bool hasnb = inv[a] > 0.f;
        float gir = hasnb ? ir[a]  + sbf[c]      : sbi[c];
        float giz = hasnb ? iz[a]  + sbf[32 + c] : sbi[32 + c];
        float gin = hasnb ? inn[a] + sbf[64 + c] : sbi[64 + c];
        float ghr = hr[a] + sbh[c];
        float ghz = hz[a] + sbh[32 + c];
        float ghn = hn[a] + sbh[64 + c];
        float rg = 1.f / (1.f + __expf(-(gir + ghr)));
        float zg = 1.f / (1.f + __expf(-(giz + ghz)));
        float ng = tanhf(gin + rg * ghn);
        float hnew = (1.f - zg) * ng + zg * hc[a];
        g_h[atom * EMB + c] = hnew;
        store_Bq(atom, c, hnew);
        if (outH) outH[atom * EMB + c] = hnew;
    }
}

// ---------------- deterministic segment mean (block per graph, tree reduce) ----------------
__global__ void k_segmean(const int* __restrict__ batch) {
    int gph = blockIdx.x;
    int t = threadIdx.x;
    float a[32];
#pragma unroll
    for (int c = 0; c < 32; c++) a[c] = 0.f;
    int cnt = 0;
    for (int j = 0; j < 32; j++) {
        int i = t + j * 256;
        if (batch[i] == gph) {
            cnt++;
            const float4* hp = reinterpret_cast<const float4*>(g_h + i * EMB);
#pragma unroll
            for (int q = 0; q < 8; q++) {
                float4 v = hp[q];
                a[q * 4] += v.x; a[q * 4 + 1] += v.y; a[q * 4 + 2] += v.z; a[q * 4 + 3] += v.w;
            }
        }
    }
    __shared__ float sa[256 * 32];
    __shared__ int sc[256];
#pragma unroll
    for (int c = 0; c < 32; c++) sa[t * 32 + c] = a[c];
    sc[t] = cnt;
    __syncthreads();
    for (int st = 128; st > 0; st >>= 1) {
        if (t < st) {
#pragma unroll
            for (int c = 0; c < 32; c++) sa[t * 32 + c] += sa[(t + st) * 32 + c];
            sc[t] += sc[t + st];
        }
        __syncthreads();
    }
    if (t < 32) {
        int n = sc[0];
        g_gm[gph * EMB + t] = n > 0 ? sa[t] / (float)n : 0.f;
    }
}

// ---------------- graph embedding GEMM (tiny) ----------------
__global__ void k_gemb(const float* __restrict__ pW, const float* __restrict__ pb,
                       float* __restrict__ out) {
    int idx = blockIdx.x * 256 + threadIdx.x;   // 256 graphs * 256 outputs
    int gph = idx >> 8, o = idx & 255;
    const float* gm = g_gm + gph * EMB;
    const float* wv = pW + o * EMB;
    float acc = pb[o];
#pragma unroll
    for (int c = 0; c < 32; c++) acc += gm[c] * wv[c];
    out[idx] = acc;
}

// ---------------- bond embedding gather ----------------
__global__ void k_bond(const int* __restrict__ bfeat, const float* __restrict__ bemb,
                       float* __restrict__ out) {
    int idx = blockIdx.x * 256 + threadIdx.x;   // 32768*32
    int b = idx >> 5, c = idx & 31;
    out[idx] = bemb[bfeat[b] * EMB + c];
}

// ---------------- launch ----------------
extern "C" void kernel_launch(void* const* d_in, const int* in_sizes, int n_in,
                              void* d_out, int out_size) {
    const int*   af       = (const int*)d_in[0];
    const int*   bfeat    = (const int*)d_in[1];
    const int*   adj      = (const int*)d_in[2];
    const int*   batch    = (const int*)d_in[3];
    const float* atom_emb = (const float*)d_in[4];
    const float* bond_emb = (const float*)d_in[5];
    const float* msg_W    = (const float*)d_in[6];
    const float* msg_b    = (const float*)d_in[7];
    const float* gWih     = (const float*)d_in[8];
    const float* gWhh     = (const float*)d_in[9];
    const float* gbih     = (const float*)d_in[10];
    const float* gbhh     = (const float*)d_in[11];
    const float* pW       = (const float*)d_in[12];
    const float* pb       = (const float*)d_in[13];
    float* out = (float*)d_out;

    k_mask<<<NA, 256>>>(adj);
    k_fold<<<dim3(24, DEPTH), 256>>>(msg_W, msg_b, gWih, gbih);
    k_embed<<<NA * EMB / 256, 256>>>(af, atom_emb);
    for (int d = 0; d < DEPTH; d++) {
        k_adj<<<dim3(NA / 64, SPLITK), 128>>>();
        k_gru<<<NA / 32, 256>>>(d, gWhh, gbih, gbhh,
                                d == DEPTH - 1 ? out + OUT_H_OFF : nullptr);
    }
    k_segmean<<<NG, 256>>>(batch);
    k_gemb<<<NG, 256>>>(pW, pb, out + OUT_GRAPH_OFF);
    k_bond<<<NBND * EMB / 256, 256>>>(bfeat, bond_emb, out + OUT_BOND_OFF);
}

// round 13
// speedup vs baseline: 1.5805x; 1.5805x over previous
#include <cuda_runtime.h>
#include <cuda_bf16.h>
#include <cstdint>

#define NA     8192
#define NBND   32768
#define NG     256
#define EMB    32
#define DEPTH  10
#define WPR    256            // 8192 bits / 32 = mask words per row
#define SPLITK 4
#define KSPLIT (NA / SPLITK)  // 2048 k per split
#define NCHUNK (KSPLIT / 128) // 16 chunks of 128 k

#define OUT_H_OFF     0
#define OUT_BOND_OFF  (NA * EMB)                 // 262144
#define OUT_GRAPH_OFF (NA * EMB + NBND * EMB)    // 1310720

// ---------------- static device scratch (no allocation) ----------------
__device__ __align__(16) unsigned int g_mask[NA * WPR];      // 8 MB bitmask (bit-permuted)
__device__ float                      g_invdeg[NA];
__device__ __align__(16) float        g_h[NA * EMB];         // current h (fp32)
// B planes, pair-interleaved b-fragment layout:
// rows = NA/4 (each row = one (ks,t) b-frag line), 64 uint2 cols (cols 0-31 hi, 32-63 lo)
// uint2.x = k-pair (ks*8+t), uint2.y = k-pair (ks*8+t+4)
__device__ __align__(16) uint2        g_B2[(NA / 4) * 64];   // 1 MB
__device__ __align__(16) float        g_nm[SPLITK * NA * EMB]; // split-K partials of A@h (4 MB)
__device__ float                      g_Wf[DEPTH * 96 * 64]; // wih @ msg_W (folded)
__device__ float                      g_bf[DEPTH * 96];      // wih @ msg_b + b_ih
__device__ float                      g_gm[NG * EMB];        // graph means

// ---------------- helpers ----------------
__device__ __forceinline__ uint32_t smem_u32(const void* p) {
    return (uint32_t)__cvta_generic_to_shared(p);
}
__device__ __forceinline__ void cp_async16(uint32_t dst, const void* src) {
    asm volatile("cp.async.ca.shared.global [%0], [%1], 16;" :: "r"(dst), "l"(src) : "memory");
}

// Bit permutation inside each 32-bit mask word so that nibble (half*4 + t)
// holds columns {16*half + 2t, 16*half + 2t + 1, 16*half + 2t + 8, 16*half + 2t + 9}.
__device__ __forceinline__ int colperm(int p) {
    int q = p & 3, n = p >> 2;
    int half = n >> 2, t = n & 3;
    return 16 * half + 2 * t + (q & 1) + ((q >> 1) << 3);
}

// ---------------- one-time: adjacency -> permuted bitmask + inv_deg ----------------
__global__ void k_mask(const int* __restrict__ adj) {
    int row = blockIdx.x;
    int warp = threadIdx.x >> 5, lane = threadIdx.x & 31;
    int cp = colperm(lane);
    const int* arow = adj + (long long)row * NA;
    int cnt = 0;
    for (int wb = 0; wb < 32; wb++) {
        int col = wb * 256 + warp * 32 + cp;
        int v = arow[col] > 0;
        cnt += v;
        unsigned bits = __ballot_sync(0xFFFFFFFFu, v);
        if (lane == 0) g_mask[row * WPR + wb * 8 + warp] = bits;
    }
    __shared__ int s[256];
    s[threadIdx.x] = cnt;
    __syncthreads();
    for (int st = 128; st > 0; st >>= 1) {
        if (threadIdx.x < st) s[threadIdx.x] += s[threadIdx.x + st];
        __syncthreads();
    }
    if (threadIdx.x == 0) {
        int deg = s[0];
        g_invdeg[row] = deg > 0 ? 1.0f / (float)deg : 0.0f;
    }
}

// ---------------- one-time: fold wih@W and wih@b + b_ih ----------------
__global__ void k_fold(const float* __restrict__ msg_W, const float* __restrict__ msg_b,
                       const float* __restrict__ wih, const float* __restrict__ bih) {
    int d = blockIdx.y;
    int idx = blockIdx.x * 256 + threadIdx.x;
    if (idx >= 96 * 64) return;
    int q = idx >> 6, kk = idx & 63;
    const float* wr = wih + (d * 96 + q) * 256;
    const float* Wc = msg_W + d * 256 * 64 + kk;
    float acc = 0.f;
#pragma unroll 8
    for (int m = 0; m < 256; m++) acc += wr[m] * Wc[m * 64];
    g_Wf[(d * 96 + q) * 64 + kk] = acc;
    if (kk == 0) {
        const float* bm = msg_b + d * 256;
        float a = 0.f;
        for (int m = 0; m < 256; m++) a += wr[m] * bm[m];
        g_bf[d * 96 + q] = a + bih[d * 96 + q];
    }
}

// ---------------- hi/lo bf16 split of h into pair-interleaved b-frag layout ----------------
// atom i: pair p = i>>1, ks = p>>3, j = p&7; row = ks*4 + (j&3); word = j>>2 (x/y);
// slot = i&1 (bf16 within the u32). Column c -> hi at col c, lo at col c+32.
__device__ __forceinline__ void store_B(int i, int c, float h) {
    __nv_bfloat16 hi = __float2bfloat16(h);
    float lof = h - __bfloat162float(hi);
    __nv_bfloat16 lo = __float2bfloat16(lof);
    int row  = (i >> 4) * 4 + ((i >> 1) & 3);
    int word = (i >> 3) & 1;
    int slot = i & 1;
    __nv_bfloat16* Bb = reinterpret_cast<__nv_bfloat16*>(g_B2);
    size_t b = ((size_t)(row * 64 + c) * 2 + word) * 2 + slot;
    Bb[b]       = hi;
    Bb[b + 128] = lo;   // col + 32 -> +32*2*2 bf16
}

// ---------------- one-time: atom embedding gather ----------------
__global__ void k_embed(const int* __restrict__ af, const float* __restrict__ emb) {
    int idx = blockIdx.x * 256 + threadIdx.x;   // 8192*32
    int i = idx >> 5, c = idx & 31;
    float h = emb[af[i] * EMB + c];
    g_h[idx] = h;
    store_B(i, c, h);
}

// ---------------- per-layer: A@h via bf16 mma.sync, A decoded from bitmask ----------------
__device__ __forceinline__ void mma16816(float* c, const unsigned int* a,
                                         unsigned int b0, unsigned int b1) {
    asm volatile(
        "mma.sync.aligned.m16n8k16.row.col.f32.bf16.bf16.f32 "
        "{%0,%1,%2,%3}, {%4,%5,%6,%7}, {%8,%9}, {%0,%1,%2,%3};"
        : "+f"(c[0]), "+f"(c[1]), "+f"(c[2]), "+f"(c[3])
        : "r"(a[0]), "r"(a[1]), "r"(a[2]), "r"(a[3]), "r"(b0), "r"(b1));
}

// CTA: 128 threads = 4 warps. CTA tile M=128 (warp M=32), N=64 (hi+lo).
// Chunk = 128 k = 32 b-frag rows; SMEM rows stride 72 uint2 (phase-disjoint banks).
__global__ void __launch_bounds__(128, 3) k_adj() {
    __shared__ uint2 sB2[2][32 * 72];   // double-buffered, 18 KB each
    __shared__ uint2 sLut16[16];        // nibble -> (a low-k pair, a high-k pair)
    int tid = threadIdx.x;
    if (tid < 16) {
        unsigned x = tid;
        unsigned w0 = (x & 1) * 0x3F80u + ((x >> 1) & 1) * 0x3F800000u;
        unsigned w1 = ((x >> 2) & 1) * 0x3F80u + ((x >> 3) & 1) * 0x3F800000u;
        sLut16[x] = make_uint2(w0, w1);
    }
    int warp = tid >> 5, lane = tid & 31;
    int g = lane >> 2, t = lane & 3, t2 = t * 2;
    int bm = blockIdx.x, sk = blockIdx.y;
    int rbase = bm * 128 + warp * 32;
    int r[4] = { rbase + g, rbase + 8 + g, rbase + 16 + g, rbase + 24 + g };

    float acc[2][8][4];
#pragma unroll
    for (int mt = 0; mt < 2; mt++)
#pragma unroll
        for (int nt = 0; nt < 8; nt++)
#pragma unroll
            for (int q = 0; q < 4; q++) acc[mt][nt][q] = 0.f;

    int kw0 = sk * (KSPLIT / 32);
    const uint2* srcbase = g_B2 + (size_t)(sk * (KSPLIT / 4)) * 64;  // split row0 * 64

    auto issue = [&](int ch) {
        uint2* dst = sB2[ch & 1];
        const uint2* src = srcbase + (size_t)ch * 32 * 64;
#pragma unroll
        for (int j = 0; j < 8; j++) {
            int e16 = tid + j * 128;           // 16-byte unit within chunk
            int rl = e16 >> 5;                 // row (32 uint2 pairs per row => 16B units /32)
            int col = (e16 & 31) * 2;
            cp_async16(smem_u32(&dst[rl * 72 + col]), &src[e16 * 2]);
        }
        asm volatile("cp.async.commit_group;" ::: "memory");
    };

    issue(0);
    uint4 mw4[4];
#pragma unroll
    for (int rr = 0; rr < 4; rr++)
        mw4[rr] = *reinterpret_cast<const uint4*>(&g_mask[r[rr] * WPR + kw0]);

    for (int ch = 0; ch < NCHUNK; ch++) {
        unsigned mw[4][4];
#pragma unroll
        for (int rr = 0; rr < 4; rr++) {
            mw[rr][0] = mw4[rr].x; mw[rr][1] = mw4[rr].y;
            mw[rr][2] = mw4[rr].z; mw[rr][3] = mw4[rr].w;
        }
        if (ch + 1 < NCHUNK) {
            issue(ch + 1);
#pragma unroll
            for (int rr = 0; rr < 4; rr++)
                mw4[rr] = *reinterpret_cast<const uint4*>(
                    &g_mask[r[rr] * WPR + kw0 + (ch + 1) * 4]);
            asm volatile("cp.async.wait_group 1;" ::: "memory");
        } else {
            asm volatile("cp.async.wait_group 0;" ::: "memory");
        }
        __syncthreads();

        const uint2* sb = sB2[ch & 1];
#pragma unroll
        for (int wrd = 0; wrd < 4; wrd++) {
#pragma unroll
            for (int half = 0; half < 2; half++) {
                int sh = half * 16 + t * 4;
                unsigned a0[4], a1[4];
                uint2 p;
                p = sLut16[(mw[0][wrd] >> sh) & 15]; a0[0] = p.x; a0[2] = p.y;
                p = sLut16[(mw[1][wrd] >> sh) & 15]; a0[1] = p.x; a0[3] = p.y;
                p = sLut16[(mw[2][wrd] >> sh) & 15]; a1[0] = p.x; a1[2] = p.y;
                p = sLut16[(mw[3][wrd] >> sh) & 15]; a1[1] = p.x; a1[3] = p.y;
                const uint2* brow = sb + ((wrd * 2 + half) * 4 + t) * 72;
#pragma unroll
                for (int nt = 0; nt < 8; nt++) {
                    uint2 b = brow[nt * 8 + g];
                    mma16816(acc[0][nt], a0, b.x, b.y);
                    mma16816(acc[1][nt], a1, b.x, b.y);
                }
            }
        }
        __syncthreads();
    }

    // epilogue: combine hi (nt 0-3) + lo (nt 4-7), write fp32 partials
    float* out = g_nm + (size_t)sk * NA * EMB;
#pragma unroll
    for (int mt = 0; mt < 2; mt++) {
#pragma unroll
        for (int nt = 0; nt < 4; nt++) {
            int row = rbase + mt * 16 + g;
            int col = nt * 8 + t2;
            float2 v0, v1;
            v0.x = acc[mt][nt][0] + acc[mt][nt + 4][0];
            v0.y = acc[mt][nt][1] + acc[mt][nt + 4][1];
            v1.x = acc[mt][nt][2] + acc[mt][nt + 4][2];
            v1.y = acc[mt][nt][3] + acc[mt][nt + 4][3];
            *reinterpret_cast<float2*>(&out[row * EMB + col]) = v0;
            *reinterpret_cast<float2*>(&out[(row + 8) * EMB + col]) = v1;
        }
    }
}

// ---------------- per-layer: fused msg-fold + GRU update (4 atoms per warp) ----------------
__global__ void __launch_bounds__(256) k_gru(int d,
        const float* __restrict__ whh, const float* __restrict__ bih,
        const float* __restrict__ bhh, float* __restrict__ outH) {
    __shared__ float sWf[64 * 97];   // transposed, pad 97 -> conflict-free
    __shared__ float sWh[32 * 97];
    __shared__ float sbf[96], sbi[96], sbh[96];
    __shared__ float sx[32][64];
    int tid = threadIdx.x;

    const float* Wf = g_Wf + d * 96 * 64;
    for (int idx = tid; idx < 96 * 64; idx += 256) {
        int q = idx >> 6, k = idx & 63;
        sWf[k * 97 + q] = Wf[idx];
    }
    const float* Wh = whh + d * 96 * 32;
    for (int idx = tid; idx < 96 * 32; idx += 256) {
        int q = idx >> 5, k = idx & 31;
        sWh[k * 97 + q] = Wh[idx];
    }
    if (tid < 96) {
        sbf[tid] = g_bf[d * 96 + tid];
        sbi[tid] = bih[d * 96 + tid];
        sbh[tid] = bhh[d * 96 + tid];
    }

    int w = tid >> 5, c = tid & 31;
    int abase = blockIdx.x * 32 + w * 4;
    float hc[4], inv[4];
#pragma unroll
    for (int a = 0; a < 4; a++) {
        int atom = abase + a;
        hc[a]  = g_h[atom * EMB + c];
        inv[a] = g_invdeg[atom];
        float nm = 0.f;
#pragma unroll
        for (int s = 0; s < SPLITK; s++)
            nm += g_nm[(size_t)s * NA * EMB + atom * EMB + c];
        sx[w * 4 + a][c]      = hc[a];
        sx[w * 4 + a][32 + c] = nm * inv[a];
    }
    __syncthreads();

    float ir[4]  = {0, 0, 0, 0}, iz[4] = {0, 0, 0, 0}, inn[4] = {0, 0, 0, 0};
    float hr[4]  = {0, 0, 0, 0}, hz[4] = {0, 0, 0, 0}, hn[4]  = {0, 0, 0, 0};
#pragma unroll 8
    for (int k = 0; k < 32; k++) {
        float wf0 = sWf[k * 97 + c], wf1 = sWf[k * 97 + 32 + c], wf2 = sWf[k * 97 + 64 + c];
        float wh0 = sWh[k * 97 + c], wh1 = sWh[k * 97 + 32 + c], wh2 = sWh[k * 97 + 64 + c];
#pragma unroll
        for (int a = 0; a < 4; a++) {
            float xk = sx[w * 4 + a][k];
            ir[a]  += xk * wf0; iz[a] += xk * wf1; inn[a] += xk * wf2;
            hr[a]  += xk * wh0; hz[a] += xk * wh1; hn[a]  += xk * wh2;
        }
    }
#pragma unroll 8
    for (int k = 32; k < 64; k++) {
        float wf0 = sWf[k * 97 + c], wf1 = sWf[k * 97 + 32 + c], wf2 = sWf[k * 97 + 64 + c];
#pragma unroll
        for (int a = 0; a < 4; a++) {
            float xk = sx[w * 4 + a][k];
            ir[a] += xk * wf0; iz[a] += xk * wf1; inn[a] += xk * wf2;
        }
    }

#pragma unroll
    for (int a = 0; a < 4; a++) {
        int atom = abase + a;
        bool hasnb = inv[a] > 0.f;
        float gir = hasnb ? ir[a]  + sbf[c]      : sbi[c];
        float giz = hasnb ? iz[a]  + sbf[32 + c] : sbi[32 + c];
        float gin = hasnb ? inn[a] + sbf[64 + c] : sbi[64 + c];
        float ghr = hr[a] + sbh[c];
        float ghz = hz[a] + sbh[32 + c];
        float ghn = hn[a] + sbh[64 + c];
        float rg = 1.f / (1.f + __expf(-(gir + ghr)));
        float zg = 1.f / (1.f + __expf(-(giz + ghz)));
        float ng = tanhf(gin + rg * ghn);
        float hnew = (1.f - zg) * ng + zg * hc[a];
        g_h[atom * EMB + c] = hnew;
        store_B(atom, c, hnew);
        if (outH) outH[atom * EMB + c] = hnew;
    }
}

// ---------------- deterministic segment mean (block per graph, tree reduce) ----------------
__global__ void k_segmean(const int* __restrict__ batch) {
    int gph = blockIdx.x;
    int t = threadIdx.x;
    float a[32];
#pragma unroll
    for (int c = 0; c < 32; c++) a[c] = 0.f;
    int cnt = 0;
    for (int j = 0; j < 32; j++) {
        int i = t + j * 256;
        if (batch[i] == gph) {
            cnt++;
            const float4* hp = reinterpret_cast<const float4*>(g_h + i * EMB);
#pragma unroll
            for (int q = 0; q < 8; q++) {
                float4 v = hp[q];
                a[q * 4] += v.x; a[q * 4 + 1] += v.y; a[q * 4 + 2] += v.z; a[q * 4 + 3] += v.w;
            }
        }
    }
    __shared__ float sa[256 * 32];
    __shared__ int sc[256];
#pragma unroll
    for (int c = 0; c < 32; c++) sa[t * 32 + c] = a[c];
    sc[t] = cnt;
    __syncthreads();
    for (int st = 128; st > 0; st >>= 1) {
        if (t < st) {
#pragma unroll
            for (int c = 0; c < 32; c++) sa[t * 32 + c] += sa[(t + st) * 32 + c];
            sc[t] += sc[t + st];
        }
        __syncthreads();
    }
    if (t < 32) {
        int n = sc[0];
        g_gm[gph * EMB + t] = n > 0 ? sa[t] / (float)n : 0.f;
    }
}

// ---------------- graph embedding GEMM (tiny) ----------------
__global__ void k_gemb(const float* __restrict__ pW, const float* __restrict__ pb,
                       float* __restrict__ out) {
    int idx = blockIdx.x * 256 + threadIdx.x;   // 256 graphs * 256 outputs
    int gph = idx >> 8, o = idx & 255;
    const float* gm = g_gm + gph * EMB;
    const float* wv = pW + o * EMB;
    float acc = pb[o];
#pragma unroll
    for (int c = 0; c < 32; c++) acc += gm[c] * wv[c];
    out[idx] = acc;
}

// ---------------- bond embedding gather ----------------
__global__ void k_bond(const int* __restrict__ bfeat, const float* __restrict__ bemb,
                       float* __restrict__ out) {
    int idx = blockIdx.x * 256 + threadIdx.x;   // 32768*32
    int b = idx >> 5, c = idx & 31;
    out[idx] = bemb[bfeat[b] * EMB + c];
}

// ---------------- launch ----------------
extern "C" void kernel_launch(void* const* d_in, const int* in_sizes, int n_in,
                              void* d_out, int out_size) {
    const int*   af       = (const int*)d_in[0];
    const int*   bfeat    = (const int*)d_in[1];
    const int*   adj      = (const int*)d_in[2];
    const int*   batch    = (const int*)d_in[3];
    const float* atom_emb = (const float*)d_in[4];
    const float* bond_emb = (const float*)d_in[5];
    const float* msg_W    = (const float*)d_in[6];
    const float* msg_b    = (const float*)d_in[7];
    const float* gWih     = (const float*)d_in[8];
    const float* gWhh     = (const float*)d_in[9];
    const float* gbih     = (const float*)d_in[10];
    const float* gbhh     = (const float*)d_in[11];
    const float* pW       = (const float*)d_in[12];
    const float* pb       = (const float*)d_in[13];
    float* out = (float*)d_out;

    k_mask<<<NA, 256>>>(adj);
    k_fold<<<dim3(24, DEPTH), 256>>>(msg_W, msg_b, gWih, gbih);
    k_embed<<<NA * EMB / 256, 256>>>(af, atom_emb);
    for (int d = 0; d < DEPTH; d++) {
        k_adj<<<dim3(NA / 128, SPLITK), 128>>>();
        k_gru<<<NA / 32, 256>>>(d, gWhh, gbih, gbhh,
                                d == DEPTH - 1 ? out + OUT_H_OFF : nullptr);
    }
    k_segmean<<<NG, 256>>>(batch);
    k_gemb<<<NG, 256>>>(pW, pb, out + OUT_GRAPH_OFF);
    k_bond<<<NBND * EMB / 256, 256>>>(bfeat, bond_emb, out + OUT_BOND_OFF);
}

// round 15
// speedup vs baseline: 1.5907x; 1.0065x over previous
#include <cuda_runtime.h>
#include <cuda_bf16.h>
#include <cstdint>

#define NA     8192
#define NBND   32768
#define NG     256
#define EMB    32
#define DEPTH  10
#define WPR    256            // 8192 bits / 32 = mask words per row
#define SPLITK 4
#define KSPLIT (NA / SPLITK)  // 2048 k per split
#define PAIRS_SPLIT (KSPLIT / 2)
#define CHUNK_PAIRS 64        // 128 k per chunk
#define NCHUNK (KSPLIT / 128) // 16

#define OUT_H_OFF     0
#define OUT_BOND_OFF  (NA * EMB)                 // 262144
#define OUT_GRAPH_OFF (NA * EMB + NBND * EMB)    // 1310720

// ---------------- static device scratch (no allocation) ----------------
__device__ __align__(16) unsigned int g_mask[NA * WPR];          // 8 MB bitmask (bit-permuted)
__device__ float                      g_invdeg[NA];
__device__ __align__(16) float        g_h[NA * EMB];             // current h
__device__ __align__(16) unsigned int g_Bp[(NA / 2) * 64];       // [pair][64] bf16x2: cols 0-31 hi(h), 32-63 lo(h)
__device__ __align__(16) float        g_nm[SPLITK * NA * EMB];   // split-K partials of A@h
__device__ float                      g_Wf[DEPTH * 96 * 64];     // wih @ msg_W (folded)
__device__ float                      g_bf[DEPTH * 96];          // wih @ msg_b + b_ih
__device__ float                      g_gm[NG * EMB];            // graph means

// Bit permutation inside each 32-bit mask word so that nibble (half*4 + t)
// holds columns {16*half + 2t, 16*half + 2t + 1, 16*half + 2t + 8, 16*half + 2t + 9}.
__device__ __forceinline__ int colperm(int p) {
    int q = p & 3, n = p >> 2;
    int half = n >> 2, t = n & 3;
    return 16 * half + 2 * t + (q & 1) + ((q >> 1) << 3);
}

// ---------------- one-time: adjacency -> permuted bitmask + inv_deg ----------------
__global__ void k_mask(const int* __restrict__ adj) {
    int row = blockIdx.x;
    int warp = threadIdx.x >> 5, lane = threadIdx.x & 31;
    int cp = colperm(lane);
    const int* arow = adj + (long long)row * NA;
    int cnt = 0;
    for (int wb = 0; wb < 32; wb++) {
        int col = wb * 256 + warp * 32 + cp;
        int v = arow[col] > 0;
        cnt += v;
        unsigned bits = __ballot_sync(0xFFFFFFFFu, v);
        if (lane == 0) g_mask[row * WPR + wb * 8 + warp] = bits;
    }
    __shared__ int s[256];
    s[threadIdx.x] = cnt;
    __syncthreads();
    for (int st = 128; st > 0; st >>= 1) {
        if (threadIdx.x < st) s[threadIdx.x] += s[threadIdx.x + st];
        __syncthreads();
    }
    if (threadIdx.x == 0) {
        int deg = s[0];
        g_invdeg[row] = deg > 0 ? 1.0f / (float)deg : 0.0f;
    }
}

// ---------------- one-time: fold wih@W and wih@b + b_ih ----------------
__global__ void k_fold(const float* __restrict__ msg_W, const float* __restrict__ msg_b,
                       const float* __restrict__ wih, const float* __restrict__ bih) {
    int d = blockIdx.y;
    int idx = blockIdx.x * 256 + threadIdx.x;
    if (idx >= 96 * 64) return;
    int q = idx >> 6, kk = idx & 63;
    const float* wr = wih + (d * 96 + q) * 256;
    const float* Wc = msg_W + d * 256 * 64 + kk;
    float acc = 0.f;
#pragma unroll 8
    for (int m = 0; m < 256; m++) acc += wr[m] * Wc[m * 64];
    g_Wf[(d * 96 + q) * 64 + kk] = acc;
    if (kk == 0) {
        const float* bm = msg_b + d * 256;
        float a = 0.f;
        for (int m = 0; m < 256; m++) a += wr[m] * bm[m];
        g_bf[d * 96 + q] = a + bih[d * 96 + q];
    }
}

// hi/lo bf16 split of h into the B (pairs) layout for the MMA
__device__ __forceinline__ void store_B(int i, int c, float h) {
    __nv_bfloat16* Bb = reinterpret_cast<__nv_bfloat16*>(g_Bp);
    __nv_bfloat16 hi = __float2bfloat16(h);
    float lo = h - __bfloat162float(hi);
    int base = (i >> 1) * 128 + (i & 1);
    Bb[base + c * 2] = hi;
    Bb[base + (c + 32) * 2] = __float2bfloat16(lo);
}

// ---------------- one-time: atom embedding gather ----------------
__global__ void k_embed(const int* __restrict__ af, const float* __restrict__ emb) {
    int idx = blockIdx.x * 256 + threadIdx.x;   // 8192*32
    int i = idx >> 5, c = idx & 31;
    float h = emb[af[i] * EMB + c];
    g_h[idx] = h;
    store_B(i, c, h);
}

// ---------------- per-layer: A@h via bf16 mma.sync, A decoded from bitmask ----------------
__device__ __forceinline__ void mma16816(float* c, const unsigned int* a,
                                         unsigned int b0, unsigned int b1) {
    asm volatile(
        "mma.sync.aligned.m16n8k16.row.col.f32.bf16.bf16.f32 "
        "{%0,%1,%2,%3}, {%4,%5,%6,%7}, {%8,%9}, {%0,%1,%2,%3};"
        : "+f"(c[0]), "+f"(c[1]), "+f"(c[2]), "+f"(c[3])
        : "r"(a[0]), "r"(a[1]), "r"(a[2]), "r"(a[3]), "r"(b0), "r"(b1));
}

// R7 structure: 128 threads = 4 warps, warp M=32, full N=64; single-buffer LDG->STS staging.
// Nibble-LUT A decode (permuted mask): one LDS.64 per 2 a-regs.
__global__ void __launch_bounds__(128, 2) k_adj() {
    __shared__ unsigned int sB[CHUNK_PAIRS * 72];   // stride 72 -> conflict-free b-frag LDS
    __shared__ uint2 sLut16[16];                    // nibble -> two bf16x2 a-regs
    int tid = threadIdx.x;
    if (tid < 16) {
        unsigned x = tid;
        unsigned w0 = (x & 1) * 0x3F80u + ((x >> 1) & 1) * 0x3F800000u;
        unsigned w1 = ((x >> 2) & 1) * 0x3F80u + ((x >> 3) & 1) * 0x3F800000u;
        sLut16[x] = make_uint2(w0, w1);
    }
    int warp = tid >> 5, lane = tid & 31;
    int g = lane >> 2, t = lane & 3, t2 = t * 2;
    int bm = blockIdx.x, sk = blockIdx.y;
    int rbase = bm * 128 + warp * 32;
    int r[4] = { rbase + g, rbase + 8 + g, rbase + 16 + g, rbase + 24 + g };

    float acc[2][8][4];
#pragma unroll
    for (int mt = 0; mt < 2; mt++)
#pragma unroll
        for (int nt = 0; nt < 8; nt++)
#pragma unroll
            for (int q = 0; q < 4; q++) acc[mt][nt][q] = 0.f;

    int kw0 = sk * (KSPLIT / 32);
    const unsigned int* Bsrc = g_Bp + (size_t)sk * PAIRS_SPLIT * 64;

    for (int ch = 0; ch < NCHUNK; ch++) {
        // mask words: 4 per row per chunk (int4)
        unsigned int mw[4][4];
#pragma unroll
        for (int rr = 0; rr < 4; rr++) {
            uint4 v = *reinterpret_cast<const uint4*>(&g_mask[r[rr] * WPR + kw0 + ch * 4]);
            mw[rr][0] = v.x; mw[rr][1] = v.y; mw[rr][2] = v.z; mw[rr][3] = v.w;
        }
        // stage B chunk into SMEM
        const uint4* src4 = reinterpret_cast<const uint4*>(Bsrc + ch * CHUNK_PAIRS * 64);
        __syncthreads();
#pragma unroll
        for (int j = 0; j < 8; j++) {
            int e4 = tid + j * 128;
            uint4 v = src4[e4];
            int elem = e4 * 4;
            int prow = elem >> 6, pcol = elem & 63;
            *reinterpret_cast<uint4*>(&sB[prow * 72 + pcol]) = v;
        }
        __syncthreads();

#pragma unroll
        for (int wrd = 0; wrd < 4; wrd++) {
#pragma unroll
            for (int half = 0; half < 2; half++) {
                int sh = half * 16 + t * 4;
                unsigned a0[4], a1[4];
                uint2 p;
                p = sLut16[(mw[0][wrd] >> sh) & 15]; a0[0] = p.x; a0[2] = p.y;
                p = sLut16[(mw[1][wrd] >> sh) & 15]; a0[1] = p.x; a0[3] = p.y;
                p = sLut16[(mw[2][wrd] >> sh) & 15]; a1[0] = p.x; a1[2] = p.y;
                p = sLut16[(mw[3][wrd] >> sh) & 15]; a1[1] = p.x; a1[3] = p.y;
                int pb = (wrd * 2 + half) * 8 + t;
#pragma unroll
                for (int nt = 0; nt < 8; nt++) {
                    unsigned b0 = sB[pb * 72 + nt * 8 + g];
                    unsigned b1 = sB[(pb + 4) * 72 + nt * 8 + g];
                    mma16816(acc[0][nt], a0, b0, b1);
                    mma16816(acc[1][nt], a1, b0, b1);
                }
            }
        }
    }

    // epilogue: combine hi (nt 0-3) + lo (nt 4-7), write fp32 partials
    float* out = g_nm + (size_t)sk * NA * EMB;
#pragma unroll
    for (int mt = 0; mt < 2; mt++) {
#pragma unroll
        for (int nt = 0; nt < 4; nt++) {
            int row = rbase + mt * 16 + g;
            int col = nt * 8 + t2;
            float2 v0, v1;
            v0.x = acc[mt][nt][0] + acc[mt][nt + 4][0];
            v0.y = acc[mt][nt][1] + acc[mt][nt + 4][1];
            v1.x = acc[mt][nt][2] + acc[mt][nt + 4][2];
            v1.y = acc[mt][nt][3] + acc[mt][nt + 4][3];
            *reinterpret_cast<float2*>(&out[row * EMB + col]) = v0;
            *reinterpret_cast<float2*>(&out[(row + 8) * EMB + col]) = v1;
        }
    }
}

// ---------------- per-layer: fused msg-fold + GRU update (4 atoms per warp) ----------------
__global__ void __launch_bounds__(256) k_gru(int d,
        const float* __restrict__ whh, const float* __restrict__ bih,
        const float* __restrict__ bhh, float* __restrict__ outH) {
    __shared__ float sWf[64 * 97];   // transposed, pad 97 -> conflict-free
    __shared__ float sWh[32 * 97];
    __shared__ float sbf[96], sbi[96], sbh[96];
    __shared__ float sx[32][64];
    int tid = threadIdx.x;

    const float* Wf = g_Wf + d * 96 * 64;
    for (int idx = tid; idx < 96 * 64; idx += 256) {
        int q = idx >> 6, k = idx & 63;
        sWf[k * 97 + q] = Wf[idx];
    }
    const float* Wh = whh + d * 96 * 32;
    for (int idx = tid; idx < 96 * 32; idx += 256) {
        int q = idx >> 5, k = idx & 31;
        sWh[k * 97 + q] = Wh[idx];
    }
    if (tid < 96) {
        sbf[tid] = g_bf[d * 96 + tid];
        sbi[tid] = bih[d * 96 + tid];
        sbh[tid] = bhh[d * 96 + tid];
    }

    int w = tid >> 5, c = tid & 31;
    int abase = blockIdx.x * 32 + w * 4;
    float hc[4], inv[4];
#pragma unroll
    for (int a = 0; a < 4; a++) {
        int atom = abase + a;
        hc[a]  = g_h[atom * EMB + c];
        inv[a] = g_invdeg[atom];
        float nm = 0.f;
#pragma unroll
        for (int s = 0; s < SPLITK; s++)
            nm += g_nm[(size_t)s * NA * EMB + atom * EMB + c];
        sx[w * 4 + a][c]      = hc[a];
        sx[w * 4 + a][32 + c] = nm * inv[a];
    }
    __syncthreads();

    float ir[4]  = {0, 0, 0, 0}, iz[4] = {0, 0, 0, 0}, inn[4] = {0, 0, 0, 0};
    float hr[4]  = {0, 0, 0, 0}, hz[4] = {0, 0, 0, 0}, hn[4]  = {0, 0, 0, 0};
#pragma unroll 8
    for (int k = 0; k < 32; k++) {
        float wf0 = sWf[k * 97 + c], wf1 = sWf[k * 97 + 32 + c], wf2 = sWf[k * 97 + 64 + c];
        float wh0 = sWh[k * 97 + c], wh1 = sWh[k * 97 + 32 + c], wh2 = sWh[k * 97 + 64 + c];
#pragma unroll
        for (int a = 0; a < 4; a++) {
            float xk = sx[w * 4 + a][k];
            ir[a]  += xk * wf0; iz[a] += xk * wf1; inn[a] += xk * wf2;
            hr[a]  += xk * wh0; hz[a] += xk * wh1; hn[a]  += xk * wh2;
        }
    }
#pragma unroll 8
    for (int k = 32; k < 64; k++) {
        float wf0 = sWf[k * 97 + c], wf1 = sWf[k * 97 + 32 + c], wf2 = sWf[k * 97 + 64 + c];
#pragma unroll
        for (int a = 0; a < 4; a++) {
            float xk = sx[w * 4 + a][k];
            ir[a] += xk * wf0; iz[a] += xk * wf1; inn[a] += xk * wf2;
        }
    }

#pragma unroll
    for (int a = 0; a < 4; a++) {
        int atom = abase + a;
        bool hasnb = inv[a] > 0.f;
        float gir = hasnb ? ir[a]  + sbf[c]      : sbi[c];
        float giz = hasnb ? iz[a]  + sbf[32 + c] : sbi[32 + c];
        float gin = hasnb ? inn[a] + sbf[64 + c] : sbi[64 + c];
        float ghr = hr[a] + sbh[c];
        float ghz = hz[a] + sbh[32 + c];
        float ghn = hn[a] + sbh[64 + c];
        float rg = 1.f / (1.f + __expf(-(gir + ghr)));
        float zg = 1.f / (1.f + __expf(-(giz + ghz)));
        float ng = tanhf(gin + rg * ghn);
        float hnew = (1.f - zg) * ng + zg * hc[a];
        g_h[atom * EMB + c] = hnew;
        store_B(atom, c, hnew);
        if (outH) outH[atom * EMB + c] = hnew;
    }
}

// ---------------- deterministic segment mean (block per graph, tree reduce) ----------------
__global__ void k_segmean(const int* __restrict__ batch) {
    int gph = blockIdx.x;
    int t = threadIdx.x;
    float a[32];
#pragma unroll
    for (int c = 0; c < 32; c++) a[c] = 0.f;
    int cnt = 0;
    for (int j = 0; j < 32; j++) {
        int i = t + j * 256;
        if (batch[i] == gph) {
            cnt++;
            const float4* hp = reinterpret_cast<const float4*>(g_h + i * EMB);
#pragma unroll
            for (int q = 0; q < 8; q++) {
                float4 v = hp[q];
                a[q * 4] += v.x; a[q * 4 + 1] += v.y; a[q * 4 + 2] += v.z; a[q * 4 + 3] += v.w;
            }
        }
    }
    __shared__ float sa[256 * 32];
    __shared__ int sc[256];
#pragma unroll
    for (int c = 0; c < 32; c++) sa[t * 32 + c] = a[c];
    sc[t] = cnt;
    __syncthreads();
    for (int st = 128; st > 0; st >>= 1) {
        if (t < st) {
#pragma unroll
            for (int c = 0; c < 32; c++) sa[t * 32 + c] += sa[(t + st) * 32 + c];
            sc[t] += sc[t + st];
        }
        __syncthreads();
    }
    if (t < 32) {
        int n = sc[0];
        g_gm[gph * EMB + t] = n > 0 ? sa[t] / (float)n : 0.f;
    }
}

// ---------------- graph embedding GEMM (tiny) ----------------
__global__ void k_gemb(const float* __restrict__ pW, const float* __restrict__ pb,
                       float* __restrict__ out) {
    int idx = blockIdx.x * 256 + threadIdx.x;   // 256 graphs * 256 outputs
    int gph = idx >> 8, o = idx & 255;
    const float* gm = g_gm + gph * EMB;
    const float* wv = pW + o * EMB;
    float acc = pb[o];
#pragma unroll
    for (int c = 0; c < 32; c++) acc += gm[c] * wv[c];
    out[idx] = acc;
}

// ---------------- bond embedding gather ----------------
__global__ void k_bond(const int* __restrict__ bfeat, const float* __restrict__ bemb,
                       float* __restrict__ out) {
    int idx = blockIdx.x * 256 + threadIdx.x;   // 32768*32
    int b = idx >> 5, c = idx & 31;
    out[idx] = bemb[bfeat[b] * EMB + c];
}

// ---------------- launch ----------------
extern "C" void kernel_launch(void* const* d_in, const int* in_sizes, int n_in,
                              void* d_out, int out_size) {
    const int*   af       = (const int*)d_in[0];
    const int*   bfeat    = (const int*)d_in[1];
    const int*   adj      = (const int*)d_in[2];
    const int*   batch    = (const int*)d_in[3];
    const float* atom_emb = (const float*)d_in[4];
    const float* bond_emb = (const float*)d_in[5];
    const float* msg_W    = (const float*)d_in[6];
    const float* msg_b    = (const float*)d_in[7];
    const float* gWih     = (const float*)d_in[8];
    const float* gWhh     = (const float*)d_in[9];
    const float* gbih     = (const float*)d_in[10];
    const float* gbhh     = (const float*)d_in[11];
    const float* pW       = (const float*)d_in[12];
    const float* pb       = (const float*)d_in[13];
    float* out = (float*)d_out;

    k_mask<<<NA, 256>>>(adj);
    k_fold<<<dim3(24, DEPTH), 256>>>(msg_W, msg_b, gWih, gbih);
    k_embed<<<NA * EMB / 256, 256>>>(af, atom_emb);
    for (int d = 0; d < DEPTH; d++) {
        k_adj<<<dim3(NA / 128, SPLITK), 128>>>();
        k_gru<<<NA / 32, 256>>>(d, gWhh, gbih, gbhh,
                                d == DEPTH - 1 ? out + OUT_H_OFF : nullptr);
    }
    k_segmean<<<NG, 256>>>(batch);
    k_gemb<<<NG, 256>>>(pW, pb, out + OUT_GRAPH_OFF);
    k_bond<<<NBND * EMB / 256, 256>>>(bfeat, bond_emb, out + OUT_BOND_OFF);
}

// round 16
// speedup vs baseline: 1.7826x; 1.1206x over previous
#include <cuda_runtime.h>
#include <cuda_bf16.h>
#include <cstdint>

#define NA     8192
#define NBND   32768
#define NG     256
#define EMB    32
#define DEPTH  10
#define WPR    256            // 8192 bits / 32 = mask words per row
#define SPLITK 4
#define KSPLIT (NA / SPLITK)  // 2048 k per split
#define PAIRS_SPLIT (KSPLIT / 2)
#define CHUNK_PAIRS 64        // 128 k per chunk
#define NCHUNK (KSPLIT / 128) // 16

#define OUT_H_OFF     0
#define OUT_BOND_OFF  (NA * EMB)                 // 262144
#define OUT_GRAPH_OFF (NA * EMB + NBND * EMB)    // 1310720

// ---------------- static device scratch (no allocation) ----------------
__device__ __align__(16) unsigned int g_mask[NA * WPR];          // 8 MB bitmask (natural bit order)
__device__ float                      g_invdeg[NA];
__device__ __align__(16) float        g_h[NA * EMB];             // current h
__device__ __align__(16) unsigned int g_Bp[(NA / 2) * 64];       // [pair][64] bf16x2: cols 0-31 hi(h), 32-63 lo(h)
__device__ __align__(16) float        g_nm[SPLITK * NA * EMB];   // split-K partials of A@h
__device__ float                      g_Wf[DEPTH * 96 * 64];     // wih @ msg_W (folded)
__device__ float                      g_bf[DEPTH * 96];          // wih @ msg_b + b_ih
__device__ float                      g_gm[NG * EMB];            // graph means

// ---------------- one-time: adjacency -> bitmask + inv_deg ----------------
__global__ void k_mask(const int* __restrict__ adj) {
    int row = blockIdx.x;
    int warp = threadIdx.x >> 5, lane = threadIdx.x & 31;
    const int* arow = adj + (long long)row * NA;
    int cnt = 0;
    for (int wb = 0; wb < 32; wb++) {
        int col = wb * 256 + warp * 32 + lane;
        int v = arow[col] > 0;
        cnt += v;
        unsigned bits = __ballot_sync(0xFFFFFFFFu, v);
        if (lane == 0) g_mask[row * WPR + wb * 8 + warp] = bits;
    }
    __shared__ int s[256];
    s[threadIdx.x] = cnt;
    __syncthreads();
    for (int st = 128; st > 0; st >>= 1) {
        if (threadIdx.x < st) s[threadIdx.x] += s[threadIdx.x + st];
        __syncthreads();
    }
    if (threadIdx.x == 0) {
        int deg = s[0];
        g_invdeg[row] = deg > 0 ? 1.0f / (float)deg : 0.0f;
    }
}

// ---------------- one-time: fold wih@W and wih@b + b_ih ----------------
__global__ void k_fold(const float* __restrict__ msg_W, const float* __restrict__ msg_b,
                       const float* __restrict__ wih, const float* __restrict__ bih) {
    int d = blockIdx.y;
    int idx = blockIdx.x * 256 + threadIdx.x;
    if (idx >= 96 * 64) return;
    int q = idx >> 6, kk = idx & 63;
    const float* wr = wih + (d * 96 + q) * 256;
    const float* Wc = msg_W + d * 256 * 64 + kk;
    float acc = 0.f;
#pragma unroll 8
    for (int m = 0; m < 256; m++) acc += wr[m] * Wc[m * 64];
    g_Wf[(d * 96 + q) * 64 + kk] = acc;
    if (kk == 0) {
        const float* bm = msg_b + d * 256;
        float a = 0.f;
        for (int m = 0; m < 256; m++) a += wr[m] * bm[m];
        g_bf[d * 96 + q] = a + bih[d * 96 + q];
    }
}

// hi/lo bf16 split of h into the B (pairs) layout for the MMA
__device__ __forceinline__ void store_B(int i, int c, float h) {
    __nv_bfloat16* Bb = reinterpret_cast<__nv_bfloat16*>(g_Bp);
    __nv_bfloat16 hi = __float2bfloat16(h);
    float lo = h - __bfloat162float(hi);
    int base = (i >> 1) * 128 + (i & 1);
    Bb[base + c * 2] = hi;
    Bb[base + (c + 32) * 2] = __float2bfloat16(lo);
}

// ---------------- one-time: atom embedding gather ----------------
__global__ void k_embed(const int* __restrict__ af, const float* __restrict__ emb) {
    int idx = blockIdx.x * 256 + threadIdx.x;   // 8192*32
    int i = idx >> 5, c = idx & 31;
    float h = emb[af[i] * EMB + c];
    g_h[idx] = h;
    store_B(i, c, h);
}

// ---------------- per-layer: A@h via bf16 mma.sync, A decoded from bitmask ----------------
__device__ __forceinline__ void mma16816(float* c, const unsigned int* a,
                                         unsigned int b0, unsigned int b1) {
    asm volatile(
        "mma.sync.aligned.m16n8k16.row.col.f32.bf16.bf16.f32 "
        "{%0,%1,%2,%3}, {%4,%5,%6,%7}, {%8,%9}, {%0,%1,%2,%3};"
        : "+f"(c[0]), "+f"(c[1]), "+f"(c[2]), "+f"(c[3])
        : "r"(a[0]), "r"(a[1]), "r"(a[2]), "r"(a[3]), "r"(b0), "r"(b1));
}

// R7-exact structure; only launch_bounds occupancy raised 2 -> 3.
__global__ void __launch_bounds__(128, 3) k_adj() {
    __shared__ unsigned int sB[CHUNK_PAIRS * 72];   // stride 72 -> conflict-free b-frag LDS
    __shared__ unsigned int sLut[4];
    int tid = threadIdx.x;
    if (tid == 0) { sLut[0] = 0u; sLut[1] = 0x3F80u; sLut[2] = 0x3F800000u; sLut[3] = 0x3F803F80u; }
    int warp = tid >> 5, lane = tid & 31;
    int g = lane >> 2, t = lane & 3, t2 = t * 2;
    int bm = blockIdx.x, sk = blockIdx.y;
    int rbase = bm * 128 + warp * 32;
    int r[4] = { rbase + g, rbase + 8 + g, rbase + 16 + g, rbase + 24 + g };

    float acc[2][8][4];
#pragma unroll
    for (int mt = 0; mt < 2; mt++)
#pragma unroll
        for (int nt = 0; nt < 8; nt++)
#pragma unroll
            for (int q = 0; q < 4; q++) acc[mt][nt][q] = 0.f;

    int kw0 = sk * (KSPLIT / 32);
    const unsigned int* Bsrc = g_Bp + (size_t)sk * PAIRS_SPLIT * 64;

    for (int ch = 0; ch < NCHUNK; ch++) {
        // mask words: 4 per row per chunk (int4)
        unsigned int mw[4][4];
#pragma unroll
        for (int rr = 0; rr < 4; rr++) {
            uint4 v = *reinterpret_cast<const uint4*>(&g_mask[r[rr] * WPR + kw0 + ch * 4]);
            mw[rr][0] = v.x; mw[rr][1] = v.y; mw[rr][2] = v.z; mw[rr][3] = v.w;
        }
        // stage B chunk into SMEM
        const uint4* src4 = reinterpret_cast<const uint4*>(Bsrc + ch * CHUNK_PAIRS * 64);
        __syncthreads();
#pragma unroll
        for (int j = 0; j < 8; j++) {
            int e4 = tid + j * 128;
            uint4 v = src4[e4];
            int elem = e4 * 4;
            int prow = elem >> 6, pcol = elem & 63;
            *reinterpret_cast<uint4*>(&sB[prow * 72 + pcol]) = v;
        }
        __syncthreads();

#pragma unroll
        for (int wrd = 0; wrd < 4; wrd++) {
#pragma unroll
            for (int half = 0; half < 2; half++) {
                int sh = half * 16 + t2;
                unsigned int a0[4], a1[4];
                a0[0] = sLut[(mw[0][wrd] >> sh) & 3];
                a0[1] = sLut[(mw[1][wrd] >> sh) & 3];
                a0[2] = sLut[(mw[0][wrd] >> (sh + 8)) & 3];
                a0[3] = sLut[(mw[1][wrd] >> (sh + 8)) & 3];
                a1[0] = sLut[(mw[2][wrd] >> sh) & 3];
                a1[1] = sLut[(mw[3][wrd] >> sh) & 3];
                a1[2] = sLut[(mw[2][wrd] >> (sh + 8)) & 3];
                a1[3] = sLut[(mw[3][wrd] >> (sh + 8)) & 3];
                int ks = wrd * 2 + half;
                int pb = ks * 8 + t;
#pragma unroll
                for (int nt = 0; nt < 8; nt++) {
                    unsigned int b0 = sB[pb * 72 + nt * 8 + g];
                    unsigned int b1 = sB[(pb + 4) * 72 + nt * 8 + g];
                    mma16816(acc[0][nt], a0, b0, b1);
                    mma16816(acc[1][nt], a1, b0, b1);
                }
            }
        }
    }

    // epilogue: combine hi (nt 0-3) + lo (nt 4-7), write fp32 partials
    float* out = g_nm + (size_t)sk * NA * EMB;
#pragma unroll
    for (int mt = 0; mt < 2; mt++) {
#pragma unroll
        for (int nt = 0; nt < 4; nt++) {
            int row = rbase + mt * 16 + g;
            int col = nt * 8 + t2;
            float2 v0, v1;
            v0.x = acc[mt][nt][0] + acc[mt][nt + 4][0];
            v0.y = acc[mt][nt][1] + acc[mt][nt + 4][1];
            v1.x = acc[mt][nt][2] + acc[mt][nt + 4][2];
            v1.y = acc[mt][nt][3] + acc[mt][nt + 4][3];
            *reinterpret_cast<float2*>(&out[row * EMB + col]) = v0;
            *reinterpret_cast<float2*>(&out[(row + 8) * EMB + col]) = v1;
        }
    }
}

// ---------------- per-layer: fused msg-fold + GRU update (4 atoms per warp) ----------------
__global__ void __launch_bounds__(256) k_gru(int d,
        const float* __restrict__ whh, const float* __restrict__ bih,
        const float* __restrict__ bhh, float* __restrict__ outH) {
    __shared__ float sWf[64 * 97];   // transposed, pad 97 -> conflict-free
    __shared__ float sWh[32 * 97];
    __shared__ float sbf[96], sbi[96], sbh[96];
    __shared__ float sx[32][64];
    int tid = threadIdx.x;

    const float* Wf = g_Wf + d * 96 * 64;
    for (int idx = tid; idx < 96 * 64; idx += 256) {
        int q = idx >> 6, k = idx & 63;
        sWf[k * 97 + q] = Wf[idx];
    }
    const float* Wh = whh + d * 96 * 32;
    for (int idx = tid; idx < 96 * 32; idx += 256) {
        int q = idx >> 5, k = idx & 31;
        sWh[k * 97 + q] = Wh[idx];
    }
    if (tid < 96) {
        sbf[tid] = g_bf[d * 96 + tid];
        sbi[tid] = bih[d * 96 + tid];
        sbh[tid] = bhh[d * 96 + tid];
    }

    int w = tid >> 5, c = tid & 31;
    int abase = blockIdx.x * 32 + w * 4;
    float hc[4], inv[4];
#pragma unroll
    for (int a = 0; a < 4; a++) {
        int atom = abase + a;
        hc[a]  = g_h[atom * EMB + c];
        inv[a] = g_invdeg[atom];
        float nm = 0.f;
#pragma unroll
        for (int s = 0; s < SPLITK; s++)
            nm += g_nm[(size_t)s * NA * EMB + atom * EMB + c];
        sx[w * 4 + a][c]      = hc[a];
        sx[w * 4 + a][32 + c] = nm * inv[a];
    }
    __syncthreads();

    float ir[4]  = {0, 0, 0, 0}, iz[4] = {0, 0, 0, 0}, inn[4] = {0, 0, 0, 0};
    float hr[4]  = {0, 0, 0, 0}, hz[4] = {0, 0, 0, 0}, hn[4]  = {0, 0, 0, 0};
#pragma unroll 8
    for (int k = 0; k < 32; k++) {
        float wf0 = sWf[k * 97 + c], wf1 = sWf[k * 97 + 32 + c], wf2 = sWf[k * 97 + 64 + c];
        float wh0 = sWh[k * 97 + c], wh1 = sWh[k * 97 + 32 + c], wh2 = sWh[k * 97 + 64 + c];
#pragma unroll
        for (int a = 0; a < 4; a++) {
            float xk = sx[w * 4 + a][k];
            ir[a]  += xk * wf0; iz[a] += xk * wf1; inn[a] += xk * wf2;
            hr[a]  += xk * wh0; hz[a] += xk * wh1; hn[a]  += xk * wh2;
        }
    }
#pragma unroll 8
    for (int k = 32; k < 64; k++) {
        float wf0 = sWf[k * 97 + c], wf1 = sWf[k * 97 + 32 + c], wf2 = sWf[k * 97 + 64 + c];
#pragma unroll
        for (int a = 0; a < 4; a++) {
            float xk = sx[w * 4 + a][k];
            ir[a] += xk * wf0; iz[a] += xk * wf1; inn[a] += xk * wf2;
        }
    }

#pragma unroll
    for (int a = 0; a < 4; a++) {
        int atom = abase + a;
        bool hasnb = inv[a] > 0.f;
        float gir = hasnb ? ir[a]  + sbf[c]      : sbi[c];
        float giz = hasnb ? iz[a]  + sbf[32 + c] : sbi[32 + c];
        float gin = hasnb ? inn[a] + sbf[64 + c] : sbi[64 + c];
        float ghr = hr[a] + sbh[c];
        float ghz = hz[a] + sbh[32 + c];
        float ghn = hn[a] + sbh[64 + c];
        float rg = 1.f / (1.f + __expf(-(gir + ghr)));
        float zg = 1.f / (1.f + __expf(-(giz + ghz)));
        float ng = tanhf(gin + rg * ghn);
        float hnew = (1.f - zg) * ng + zg * hc[a];
        g_h[atom * EMB + c] = hnew;
        store_B(atom, c, hnew);
        if (outH) outH[atom * EMB + c] = hnew;
    }
}

// ---------------- deterministic segment mean (block per graph, tree reduce) ----------------
__global__ void k_segmean(const int* __restrict__ batch) {
    int gph = blockIdx.x;
    int t = threadIdx.x;
    float a[32];
#pragma unroll
    for (int c = 0; c < 32; c++) a[c] = 0.f;
    int cnt = 0;
    for (int j = 0; j < 32; j++) {
        int i = t + j * 256;
        if (batch[i] == gph) {
            cnt++;
            const float4* hp = reinterpret_cast<const float4*>(g_h + i * EMB);
#pragma unroll
            for (int q = 0; q < 8; q++) {
                float4 v = hp[q];
                a[q * 4] += v.x; a[q * 4 + 1] += v.y; a[q * 4 + 2] += v.z; a[q * 4 + 3] += v.w;
            }
        }
    }
    __shared__ float sa[256 * 32];
    __shared__ int sc[256];
#pragma unroll
    for (int c = 0; c < 32; c++) sa[t * 32 + c] = a[c];
    sc[t] = cnt;
    __syncthreads();
    for (int st = 128; st > 0; st >>= 1) {
        if (t < st) {
#pragma unroll
            for (int c = 0; c < 32; c++) sa[t * 32 + c] += sa[(t + st) * 32 + c];
            sc[t] += sc[t + st];
        }
        __syncthreads();
    }
    if (t < 32) {
        int n = sc[0];
        g_gm[gph * EMB + t] = n > 0 ? sa[t] / (float)n : 0.f;
    }
}

// ---------------- graph embedding GEMM (tiny) ----------------
__global__ void k_gemb(const float* __restrict__ pW, const float* __restrict__ pb,
                       float* __restrict__ out) {
    int idx = blockIdx.x * 256 + threadIdx.x;   // 256 graphs * 256 outputs
    int gph = idx >> 8, o = idx & 255;
    const float* gm = g_gm + gph * EMB;
    const float* wv = pW + o * EMB;
    float acc = pb[o];
#pragma unroll
    for (int c = 0; c < 32; c++) acc += gm[c] * wv[c];
    out[idx] = acc;
}

// ---------------- bond embedding gather ----------------
__global__ void k_bond(const int* __restrict__ bfeat, const float* __restrict__ bemb,
                       float* __restrict__ out) {
    int idx = blockIdx.x * 256 + threadIdx.x;   // 32768*32
    int b = idx >> 5, c = idx & 31;
    out[idx] = bemb[bfeat[b] * EMB + c];
}

// ---------------- launch ----------------
extern "C" void kernel_launch(void* const* d_in, const int* in_sizes, int n_in,
                              void* d_out, int out_size) {
    const int*   af       = (const int*)d_in[0];
    const int*   bfeat    = (const int*)d_in[1];
    const int*   adj      = (const int*)d_in[2];
    const int*   batch    = (const int*)d_in[3];
    const float* atom_emb = (const float*)d_in[4];
    const float* bond_emb = (const float*)d_in[5];
    const float* msg_W    = (const float*)d_in[6];
    const float* msg_b    = (const float*)d_in[7];
    const float* gWih     = (const float*)d_in[8];
    const float* gWhh     = (const float*)d_in[9];
    const float* gbih     = (const float*)d_in[10];
    const float* gbhh     = (const float*)d_in[11];
    const float* pW       = (const float*)d_in[12];
    const float* pb       = (const float*)d_in[13];
    float* out = (float*)d_out;

    k_mask<<<NA, 256>>>(adj);
    k_fold<<<dim3(24, DEPTH), 256>>>(msg_W, msg_b, gWih, gbih);
    k_embed<<<NA * EMB / 256, 256>>>(af, atom_emb);
    for (int d = 0; d < DEPTH; d++) {
        k_adj<<<dim3(NA / 128, SPLITK), 128>>>();
        k_gru<<<NA / 32, 256>>>(d, gWhh, gbih, gbhh,
                                d == DEPTH - 1 ? out + OUT_H_OFF : nullptr);
    }
    k_segmean<<<NG, 256>>>(batch);
    k_gemb<<<NG, 256>>>(pW, pb, out + OUT_GRAPH_OFF);
    k_bond<<<NBND * EMB / 256, 256>>>(bfeat, bond_emb, out + OUT_BOND_OFF);
}